// round 16
// baseline (speedup 1.0000x reference)
#include <cuda_runtime.h>
#include <math.h>

// Problem constants (fixed by setup_inputs): bs=16, C=256, H=W=128
#define BS 16
#define CC 256
#define NN 16384           // H*W
#define TOPK 12
#define MCHUNKS 16         // mask kernel chunks per batch
#define QH 4               // row quarters in sum kernel
#define QSZ 4096           // elements per quarter

typedef unsigned long long ull;

// ---------------- scratch (device globals; no allocation allowed) ----------
__device__ __align__(16) float g_fmask_fg[BS][NN];   // 1 MB: fg mask as 0.0/1.0
__device__ __align__(16) float g_fmask_bg[BS][NN];   // 1 MB: bg mask as 0.0/1.0
__device__ int   g_part_cf[BS][MCHUNKS];
__device__ int   g_part_cb[BS][MCHUNKS];
__device__ int   g_part_bad[BS][MCHUNKS];
__device__ int   g_cnt[2][BS];                       // folded by last mask block
__device__ int   g_flagbad[BS];                      // folded by last mask block
__device__ float g_fallback[2][BS][CC];              // topk means (written only if cnt==0)
__device__ float g_ptot[QH][BS][CC];                 // per-quarter partial sums
__device__ float g_pfg[QH][BS][CC];
__device__ float g_pbg[QH][BS][CC];
__device__ int   g_arrive_mask;                      // arrival counters (self-resetting)
__device__ int   g_arrive_sum[BS];
__device__ float g_tkv[256 * TOPK];                  // cold topk scratch (global, not smem)
__device__ int   g_tki[256 * TOPK];

// ---------------- packed f32x2 helpers (ptxas won't auto-fuse) -------------
__device__ __forceinline__ ull add2(ull a, ull b) {
    ull d; asm("add.rn.f32x2 %0, %1, %2;" : "=l"(d) : "l"(a), "l"(b)); return d;
}
__device__ __forceinline__ ull fma2(ull a, ull b, ull c) {
    ull d; asm("fma.rn.f32x2 %0, %1, %2, %3;" : "=l"(d) : "l"(a), "l"(b), "l"(c)); return d;
}
__device__ __forceinline__ float up_sum(ull v) {
    float x, y; asm("mov.b64 {%0, %1}, %2;" : "=f"(x), "=f"(y) : "l"(v)); return x + y;
}

// ---------------------------------------------------------------------------
// Exact top-12 fallback for one (b, side) — runs inside the last mask block
// only when cnt==0 (never observed with this data, but exact).
// Block-wide: 256 threads. Scratch lives in GLOBAL memory (cold path) so the
// hot mask kernel carries no 28 KB smem footprint.
// ---------------------------------------------------------------------------
__device__ void topk_fallback(const float* __restrict__ outp,
                              const float* __restrict__ feat,
                              int b, int side,
                              float* sv, int* si) {
    const int t = threadIdx.x;
    const float* o0 = outp + (size_t)b * (2 * NN);
    const float* o1 = o0 + NN;

    float v[TOPK];
    int   ix[TOPK];
    #pragma unroll
    for (int k = 0; k < TOPK; k++) { v[k] = -INFINITY; ix[k] = 0x7fffffff; }

    for (int j = t; j < NN; j += 256) {
        const float a  = o0[j];
        const float b1 = o1[j];
        const float m  = fmaxf(a, b1);
        const float e0 = expf(a - m);
        const float e1 = expf(b1 - m);
        const float s  = e0 + e1;
        const float p  = (side == 0) ? (e1 / s) : (e0 / s);
        if ((p > v[TOPK - 1]) || (p == v[TOPK - 1] && j < ix[TOPK - 1])) {
            int k = TOPK - 1;
            while (k > 0 && ((p > v[k - 1]) || (p == v[k - 1] && j < ix[k - 1]))) {
                v[k] = v[k - 1]; ix[k] = ix[k - 1]; k--;
            }
            v[k] = p; ix[k] = j;
        }
    }

    #pragma unroll
    for (int k = 0; k < TOPK; k++) { sv[t * TOPK + k] = v[k]; si[t * TOPK + k] = ix[k]; }
    __syncthreads();

    for (int stride = 128; stride > 0; stride >>= 1) {
        if (t < stride) {
            float* A  = &sv[t * TOPK];
            int*   Ai = &si[t * TOPK];
            float* B  = &sv[(t + stride) * TOPK];
            int*   Bi = &si[(t + stride) * TOPK];
            float mv[TOPK]; int mi[TOPK];
            int i = 0, j = 0;
            #pragma unroll
            for (int o = 0; o < TOPK; o++) {
                const float av = A[i], bv = B[j];
                const int aix = Ai[i], bix = Bi[j];
                const bool takeA = (av > bv) || (av == bv && aix <= bix);
                if (takeA) { mv[o] = av; mi[o] = aix; i++; }
                else       { mv[o] = bv; mi[o] = bix; j++; }
            }
            #pragma unroll
            for (int o = 0; o < TOPK; o++) { A[o] = mv[o]; Ai[o] = mi[o]; }
        }
        __syncthreads();
    }

    // Gather fallback means for all 256 channels (thread t = channel t)
    const float* rowc = feat + (((size_t)b * CC + t) << 14);
    float s = 0.0f;
    #pragma unroll
    for (int k = 0; k < TOPK; k++) s += rowc[si[k]];
    g_fallback[side][b][t] = s * (1.0f / 12.0f);
    __syncthreads();
}

// ---------------------------------------------------------------------------
// Kernel 1: softmax -> float masks + partial counts; the LAST arriving block
// folds g_cnt/g_flagbad and handles the rare topk fallback inline.
// Every exit path fires griddepcontrol.launch_dependents (PDL trigger) so the
// sum kernel can be dispatched early; its wait still sees all writes here.
// grid = (16, 16) = 256 blocks, block = 256, one float4/thread.
// ---------------------------------------------------------------------------
__global__ void __launch_bounds__(256) mask_kernel(const float* __restrict__ outp,
                                                   const float* __restrict__ tau_p,
                                                   const float* __restrict__ feat) {
    __shared__ int rf8[8], rb8[8], rd8[8];
    __shared__ int s_last;
    __shared__ int s_cf[BS], s_cb[BS];

    const int b  = blockIdx.x;
    const int ch = blockIdx.y;
    const int t  = threadIdx.x;

    const float tau = *tau_p;
    const float Tf  = 1.0f / (1.0f + expf(-tau));   // sigmoid(tau)
    const float Tb  = 1.0f - Tf;

    const int base = ch * 1024;                     // 1024 elements per block
    const float4* o0 = (const float4*)(outp + (size_t)b * (2 * NN) + base);
    const float4* o1 = (const float4*)(outp + (size_t)b * (2 * NN) + NN + base);

    const float4 a  = o0[t];
    const float4 b1 = o1[t];

    float4 mf, mb;
    int cf = 0, cb = 0, bad = 0;
    {
        const float av[4] = {a.x, a.y, a.z, a.w};
        const float bv[4] = {b1.x, b1.y, b1.z, b1.w};
        float rf[4], rb[4];
        #pragma unroll
        for (int k = 0; k < 4; k++) {
            const float m  = fmaxf(av[k], bv[k]);
            const float e0 = expf(av[k] - m);
            const float e1 = expf(bv[k] - m);
            const float s  = e0 + e1;
            const float pf = e1 / s;                // softmax channel 1 (fg)
            const float pb = e0 / s;                // softmax channel 0 (bg)
            const bool ff = pf > Tf;
            const bool fb = pb > Tb;
            rf[k] = ff ? 1.0f : 0.0f;
            rb[k] = fb ? 1.0f : 0.0f;
            cf += ff; cb += fb;
            bad += (ff == fb);
        }
        mf.x = rf[0]; mf.y = rf[1]; mf.z = rf[2]; mf.w = rf[3];
        mb.x = rb[0]; mb.y = rb[1]; mb.z = rb[2]; mb.w = rb[3];
    }
    ((float4*)(&g_fmask_fg[b][base]))[t] = mf;
    ((float4*)(&g_fmask_bg[b][base]))[t] = mb;

    // block reduce partial counts
    #pragma unroll
    for (int o = 16; o > 0; o >>= 1) {
        cf  += __shfl_down_sync(0xffffffffu, cf,  o);
        cb  += __shfl_down_sync(0xffffffffu, cb,  o);
        bad += __shfl_down_sync(0xffffffffu, bad, o);
    }
    const int w = t >> 5, l = t & 31;
    if (l == 0) { rf8[w] = cf; rb8[w] = cb; rd8[w] = bad; }
    __syncthreads();
    if (t == 0) {
        int A = 0, B2 = 0, D = 0;
        #pragma unroll
        for (int i = 0; i < 8; i++) { A += rf8[i]; B2 += rb8[i]; D += rd8[i]; }
        g_part_cf[b][ch]  = A;
        g_part_cb[b][ch]  = B2;
        g_part_bad[b][ch] = D;
        __threadfence();
        const int old = atomicAdd(&g_arrive_mask, 1);
        s_last = (old == BS * MCHUNKS - 1) ? 1 : 0;
    }
    __syncthreads();
    if (!s_last) {
        asm volatile("griddepcontrol.launch_dependents;");
        return;
    }

    // ---- last block: fold counts; rare topk fallback ----
    if (t < BS) {
        int A = 0, B2 = 0, D = 0;
        #pragma unroll
        for (int i = 0; i < MCHUNKS; i++) {
            A += g_part_cf[t][i]; B2 += g_part_cb[t][i]; D += g_part_bad[t][i];
        }
        g_cnt[0][t]  = A;
        g_cnt[1][t]  = B2;
        g_flagbad[t] = D;
        s_cf[t] = A; s_cb[t] = B2;
    }
    if (t == 0) g_arrive_mask = 0;    // reset for next graph replay
    __syncthreads();

    for (int bb = 0; bb < BS; bb++) {
        if (s_cf[bb] == 0) topk_fallback(outp, feat, bb, 0, g_tkv, g_tki);
        if (s_cb[bb] == 0) topk_fallback(outp, feat, bb, 1, g_tkv, g_tki);
    }
    __threadfence();
    asm volatile("griddepcontrol.launch_dependents;");
}

// ---------------------------------------------------------------------------
// Kernel 2: the 268 MB streaming pass -> per-quarter partial sums; the LAST
// arriving block per batch b folds partials and writes that batch's outputs.
// grid = (32, 4, 16): cg, quarter h, b. block = 256 (8 warps).
// Changes vs R14: (1) feat loads use __ldcs (evict-first; feat is read once,
// protects hot mask quarters in L2); (2) first 4 feat iterations are
// prefetched into registers BEFORE the mask staging + __syncthreads, so the
// staging barrier wait overlaps the feat DRAM latency instead of stalling the
// stream; (3) PDL wait at entry.
// ---------------------------------------------------------------------------
__global__ void __launch_bounds__(256, 5) sum_kernel(const float* __restrict__ feat,
                                                     float* __restrict__ outp) {
    __shared__ __align__(16) float s_m[QSZ];   // 16 KB: quarter of one mask row
    __shared__ int s_bad, s_last;

    asm volatile("griddepcontrol.wait;");      // PDL: mask_kernel writes visible

    const int t    = threadIdx.x;
    const int w    = t >> 5;
    const int lane = t & 31;
    const int cg   = blockIdx.x;
    const int h    = blockIdx.y;
    const int b    = blockIdx.z;
    const int c    = cg * 8 + w;

    const longlong2* rv = (const longlong2*)(feat + (((size_t)b * CC + c) << 14) + h * QSZ);

    // prefetch first 4 feat iterations (independent of smem) -> overlap barrier
    longlong2 pf0 = __ldcs(&rv[0 * 32 + lane]);
    longlong2 pf1 = __ldcs(&rv[1 * 32 + lane]);
    longlong2 pf2 = __ldcs(&rv[2 * 32 + lane]);
    longlong2 pf3 = __ldcs(&rv[3 * 32 + lane]);

    if (t == 0) s_bad = g_flagbad[b];
    // stage quarter of the fg float-mask row into smem (all 256 threads)
    {
        const float4* src = (const float4*)(&g_fmask_fg[b][h * QSZ]);
        float4*       dst = (float4*)s_m;
        #pragma unroll
        for (int j = 0; j < 4; j++) dst[j * 256 + t] = src[j * 256 + t];
    }
    __syncthreads();
    const bool bad = (s_bad != 0);

    const longlong2* bv  = (const longlong2*)(&g_fmask_bg[b][h * QSZ]);
    const longlong2* smv = (const longlong2*)s_m;

    ull t2a = 0ull, t2b = 0ull;   // packed running totals
    ull f2a = 0ull, f2b = 0ull;   // packed fg sums
    ull g2a = 0ull, g2b = 0ull;   // packed bg sums (bad path only)

    if (!bad) {
        // consume prefetched iterations 0..3 (same parity pattern as loop)
        {
            const longlong2 m0 = smv[0 * 32 + lane];
            t2a = add2(t2a, add2((ull)pf0.x, (ull)pf0.y));
            f2a = fma2((ull)pf0.x, (ull)m0.x, f2a);
            f2a = fma2((ull)pf0.y, (ull)m0.y, f2a);
            const longlong2 m1 = smv[1 * 32 + lane];
            t2b = add2(t2b, add2((ull)pf1.x, (ull)pf1.y));
            f2b = fma2((ull)pf1.x, (ull)m1.x, f2b);
            f2b = fma2((ull)pf1.y, (ull)m1.y, f2b);
            const longlong2 m2 = smv[2 * 32 + lane];
            t2a = add2(t2a, add2((ull)pf2.x, (ull)pf2.y));
            f2a = fma2((ull)pf2.x, (ull)m2.x, f2a);
            f2a = fma2((ull)pf2.y, (ull)m2.y, f2a);
            const longlong2 m3 = smv[3 * 32 + lane];
            t2b = add2(t2b, add2((ull)pf3.x, (ull)pf3.y));
            f2b = fma2((ull)pf3.x, (ull)m3.x, f2b);
            f2b = fma2((ull)pf3.y, (ull)m3.y, f2b);
        }
        #pragma unroll 4
        for (int it = 4; it < 32; it++) {
            const longlong2 f = __ldcs(&rv[it * 32 + lane]);
            const longlong2 m = smv[it * 32 + lane];
            if (it & 1) {
                t2b = add2(t2b, add2((ull)f.x, (ull)f.y));
                f2b = fma2((ull)f.x, (ull)m.x, f2b);
                f2b = fma2((ull)f.y, (ull)m.y, f2b);
            } else {
                t2a = add2(t2a, add2((ull)f.x, (ull)f.y));
                f2a = fma2((ull)f.x, (ull)m.x, f2a);
                f2a = fma2((ull)f.y, (ull)m.y, f2a);
            }
        }
    } else {
        // cold path (threshold tie somewhere in batch b): direct fg+bg sums
        {
            const longlong2 m0 = smv[0 * 32 + lane];
            const longlong2 n0 = bv[0 * 32 + lane];
            f2a = fma2((ull)pf0.x, (ull)m0.x, f2a);
            f2a = fma2((ull)pf0.y, (ull)m0.y, f2a);
            g2a = fma2((ull)pf0.x, (ull)n0.x, g2a);
            g2a = fma2((ull)pf0.y, (ull)n0.y, g2a);
            const longlong2 m1 = smv[1 * 32 + lane];
            const longlong2 n1 = bv[1 * 32 + lane];
            f2b = fma2((ull)pf1.x, (ull)m1.x, f2b);
            f2b = fma2((ull)pf1.y, (ull)m1.y, f2b);
            g2b = fma2((ull)pf1.x, (ull)n1.x, g2b);
            g2b = fma2((ull)pf1.y, (ull)n1.y, g2b);
            const longlong2 m2 = smv[2 * 32 + lane];
            const longlong2 n2 = bv[2 * 32 + lane];
            f2a = fma2((ull)pf2.x, (ull)m2.x, f2a);
            f2a = fma2((ull)pf2.y, (ull)m2.y, f2a);
            g2a = fma2((ull)pf2.x, (ull)n2.x, g2a);
            g2a = fma2((ull)pf2.y, (ull)n2.y, g2a);
            const longlong2 m3 = smv[3 * 32 + lane];
            const longlong2 n3 = bv[3 * 32 + lane];
            f2b = fma2((ull)pf3.x, (ull)m3.x, f2b);
            f2b = fma2((ull)pf3.y, (ull)m3.y, f2b);
            g2b = fma2((ull)pf3.x, (ull)n3.x, g2b);
            g2b = fma2((ull)pf3.y, (ull)n3.y, g2b);
        }
        #pragma unroll 4
        for (int it = 4; it < 32; it++) {
            const longlong2 f  = __ldcs(&rv[it * 32 + lane]);
            const longlong2 m  = smv[it * 32 + lane];
            const longlong2 mb = bv[it * 32 + lane];
            if (it & 1) {
                f2b = fma2((ull)f.x, (ull)m.x,  f2b);
                f2b = fma2((ull)f.y, (ull)m.y,  f2b);
                g2b = fma2((ull)f.x, (ull)mb.x, g2b);
                g2b = fma2((ull)f.y, (ull)mb.y, g2b);
            } else {
                f2a = fma2((ull)f.x, (ull)m.x,  f2a);
                f2a = fma2((ull)f.y, (ull)m.y,  f2a);
                g2a = fma2((ull)f.x, (ull)mb.x, g2a);
                g2a = fma2((ull)f.y, (ull)mb.y, g2a);
            }
        }
    }

    // unpack + warp reduce (one (c, quarter) per warp)
    float tot = up_sum(t2a) + up_sum(t2b);
    float fg  = up_sum(f2a) + up_sum(f2b);
    float bg  = up_sum(g2a) + up_sum(g2b);
    #pragma unroll
    for (int o = 16; o > 0; o >>= 1) {
        tot += __shfl_down_sync(0xffffffffu, tot, o);
        fg  += __shfl_down_sync(0xffffffffu, fg,  o);
        bg  += __shfl_down_sync(0xffffffffu, bg,  o);
    }
    if (lane == 0) {
        g_ptot[h][b][c] = tot;
        g_pfg[h][b][c]  = fg;
        g_pbg[h][b][c]  = bg;
    }
    __syncthreads();            // all warps' partial stores issued
    if (t == 0) {
        __threadfence();
        const int old = atomicAdd(&g_arrive_sum[b], 1);
        s_last = (old == 32 * QH - 1) ? 1 : 0;
    }
    __syncthreads();
    if (!s_last) return;

    // ---- last block for batch b: fold quarters -> output (thread = channel) ----
    const int cf2 = g_cnt[0][b];
    const int cb2 = g_cnt[1][b];
    float T = 0.0f, F = 0.0f, Bg = 0.0f;
    #pragma unroll
    for (int hq = 0; hq < QH; hq++) {
        T  += g_ptot[hq][b][t];
        F  += g_pfg[hq][b][t];
        Bg += g_pbg[hq][b][t];
    }
    const float bgs = bad ? Bg : (T - F);
    const float vf = (cf2 > 0) ? F   / (float)cf2 : g_fallback[0][b][t];
    const float vb = (cb2 > 0) ? bgs / (float)cb2 : g_fallback[1][b][t];
    outp[b * CC + t]        = vf;   // fg_proto
    outp[4096 + b * CC + t] = vb;   // bg_proto

    if (t == 0) g_arrive_sum[b] = 0;   // reset for next graph replay
}

// ---------------------------------------------------------------------------
extern "C" void kernel_launch(void* const* d_in, const int* in_sizes, int n_in,
                              void* d_out, int out_size) {
    (void)in_sizes; (void)n_in; (void)out_size;
    const float* feat = (const float*)d_in[0];   // (16,256,128,128) f32
    const float* outv = (const float*)d_in[1];   // (16,2,128,128)   f32
    const float* tau  = (const float*)d_in[2];   // scalar f32
    float* outp = (float*)d_out;                 // 8192 f32: fg(4096) ++ bg(4096)

    mask_kernel<<<dim3(BS, MCHUNKS), 256>>>(outv, tau, feat);

    // PDL launch: sum_kernel may be dispatched before mask_kernel fully
    // retires; its griddepcontrol.wait blocks until the producer triggers.
    cudaLaunchConfig_t cfg = {};
    cfg.gridDim  = dim3(32, QH, BS);
    cfg.blockDim = dim3(256, 1, 1);
    cudaLaunchAttribute attr[1];
    attr[0].id = cudaLaunchAttributeProgrammaticStreamSerialization;
    attr[0].val.programmaticStreamSerializationAllowed = 1;
    cfg.attrs = attr;
    cfg.numAttrs = 1;
    cudaLaunchKernelEx(&cfg, sum_kernel, feat, outp);
}